// round 4
// baseline (speedup 1.0000x reference)
#include <cuda_runtime.h>
#include <float.h>

// SparseSoftmax: masked softmax over last axis of (32, 2048, 2048) fp32
// with int32 mask (mask = OD != 0). Fully-masked rows -> zeros.
//
// R4: one CTA of 512 threads per row, 4 elements/thread (1 float4 + 1 int4).
// Rationale: halves MLP_p1 (front-batched LDG.128 count) from 4 -> 2, putting
// oe*MLP_p1 at the L1tex-queue contention threshold and minimizing cross-CTA
// completion spread, while keeping total in-flight load count and occupancy.

#define ROW_LEN 2048
#define THREADS 512
#define NWARPS  (THREADS / 32)   // 16

__global__ __launch_bounds__(THREADS, 4)
void sparse_softmax_kernel(const float* __restrict__ f,
                           const int* __restrict__ od,
                           float* __restrict__ out)
{
    const int row = blockIdx.x;
    const size_t base = (size_t)row * ROW_LEN;
    const float4* __restrict__ f4 = reinterpret_cast<const float4*>(f + base);
    const int4*   __restrict__ o4 = reinterpret_cast<const int4*>(od + base);
    float4* __restrict__ out4 = reinterpret_cast<float4*>(out + base);

    const int t    = threadIdx.x;
    const int warp = t >> 5;
    const int lane = t & 31;

    // One float4 + one int4 per thread: MLP_p1 = 2.
    float4 v = __ldcs(&f4[t]);
    int4   m = __ldcs(&o4[t]);

    float vals[4] = {v.x, v.y, v.z, v.w};
    int   msk [4] = {m.x, m.y, m.z, m.w};

    __shared__ float smax[NWARPS];
    __shared__ float ssum[NWARPS];

    // --- local + warp max over unmasked lanes ---
    float mx = -FLT_MAX;
    #pragma unroll
    for (int i = 0; i < 4; i++)
        if (msk[i] != 0) mx = fmaxf(mx, vals[i]);
    #pragma unroll
    for (int o = 16; o > 0; o >>= 1)
        mx = fmaxf(mx, __shfl_xor_sync(0xffffffffu, mx, o));
    if (lane == 0) smax[warp] = mx;
    __syncthreads();

    // Every thread reduces the 16 partials itself (broadcast LDS).
    float rowmax = smax[0];
    #pragma unroll
    for (int w = 1; w < NWARPS; w++) rowmax = fmaxf(rowmax, smax[w]);

    // --- exp + sum (exp only on unmasked lanes; vals - rowmax <= 0) ---
    float p[4];
    float sum = 0.0f;
    #pragma unroll
    for (int i = 0; i < 4; i++) {
        float e = (msk[i] != 0) ? __expf(vals[i] - rowmax) : 0.0f;
        p[i] = e;
        sum += e;
    }
    #pragma unroll
    for (int o = 16; o > 0; o >>= 1)
        sum += __shfl_xor_sync(0xffffffffu, sum, o);
    if (lane == 0) ssum[warp] = sum;
    __syncthreads();

    float s = ssum[0];
    #pragma unroll
    for (int w = 1; w < NWARPS; w++) s += ssum[w];
    const float inv = (s > 0.0f) ? (1.0f / s) : 0.0f;   // fully-masked -> zeros

    // --- normalize + streaming write ---
    __stcs(&out4[t], make_float4(p[0] * inv, p[1] * inv, p[2] * inv, p[3] * inv));
}

extern "C" void kernel_launch(void* const* d_in, const int* in_sizes, int n_in,
                              void* d_out, int out_size)
{
    const float* features = (const float*)d_in[0];
    const int*   OD       = (const int*)d_in[1];
    float*       out      = (float*)d_out;

    const int rows = in_sizes[0] / ROW_LEN;   // 32*2048 = 65536
    sparse_softmax_kernel<<<rows, THREADS>>>(features, OD, out);
}

// round 5
// speedup vs baseline: 1.0995x; 1.0995x over previous
#include <cuda_runtime.h>
#include <float.h>

// SparseSoftmax: masked softmax over last axis of (32, 2048, 2048) fp32
// with int32 mask (mask = OD != 0). Fully-masked rows -> zeros.
//
// R5: one CTA of 128 threads per row, 16 elements/thread (4 float4 + 4 int4
// front-batched loads => MLP_p1 = 8). Empirically DRAM% rises monotonically
// with per-warp MLP (2->77%, 4->90%). Mask folded into vals as -inf at load
// time so no mask registers stay live; exp(-inf) = 0 handles masked lanes.

#define ROW_LEN 2048
#define THREADS 128
#define EPT     16
#define NWARPS  (THREADS / 32)   // 4

__global__ __launch_bounds__(THREADS)
void sparse_softmax_kernel(const float* __restrict__ f,
                           const int* __restrict__ od,
                           float* __restrict__ out)
{
    const int row = blockIdx.x;
    const size_t base = (size_t)row * ROW_LEN;
    const float4* __restrict__ f4 = reinterpret_cast<const float4*>(f + base);
    const int4*   __restrict__ o4 = reinterpret_cast<const int4*>(od + base);
    float4* __restrict__ out4 = reinterpret_cast<float4*>(out + base);

    const int t    = threadIdx.x;
    const int warp = t >> 5;
    const int lane = t & 31;
    const float NEG_INF = __int_as_float(0xff800000);

    // Front-batched loads: 4x LDG.128 (features) + 4x LDG.128 (mask).
    float4 v0 = __ldcs(&f4[t]);
    float4 v1 = __ldcs(&f4[t + THREADS]);
    float4 v2 = __ldcs(&f4[t + 2 * THREADS]);
    float4 v3 = __ldcs(&f4[t + 3 * THREADS]);
    int4   m0 = __ldcs(&o4[t]);
    int4   m1 = __ldcs(&o4[t + THREADS]);
    int4   m2 = __ldcs(&o4[t + 2 * THREADS]);
    int4   m3 = __ldcs(&o4[t + 3 * THREADS]);

    // Fold mask into values: masked-out lanes become -inf (mask regs die here).
    float vals[EPT];
    vals[ 0] = m0.x ? v0.x : NEG_INF;  vals[ 1] = m0.y ? v0.y : NEG_INF;
    vals[ 2] = m0.z ? v0.z : NEG_INF;  vals[ 3] = m0.w ? v0.w : NEG_INF;
    vals[ 4] = m1.x ? v1.x : NEG_INF;  vals[ 5] = m1.y ? v1.y : NEG_INF;
    vals[ 6] = m1.z ? v1.z : NEG_INF;  vals[ 7] = m1.w ? v1.w : NEG_INF;
    vals[ 8] = m2.x ? v2.x : NEG_INF;  vals[ 9] = m2.y ? v2.y : NEG_INF;
    vals[10] = m2.z ? v2.z : NEG_INF;  vals[11] = m2.w ? v2.w : NEG_INF;
    vals[12] = m3.x ? v3.x : NEG_INF;  vals[13] = m3.y ? v3.y : NEG_INF;
    vals[14] = m3.z ? v3.z : NEG_INF;  vals[15] = m3.w ? v3.w : NEG_INF;

    __shared__ float smax[NWARPS];
    __shared__ float ssum[NWARPS];

    // --- max reduce (masked lanes are -inf, harmless) ---
    float mx = NEG_INF;
    #pragma unroll
    for (int i = 0; i < EPT; i++) mx = fmaxf(mx, vals[i]);
    #pragma unroll
    for (int o = 16; o > 0; o >>= 1)
        mx = fmaxf(mx, __shfl_xor_sync(0xffffffffu, mx, o));
    if (lane == 0) smax[warp] = mx;
    __syncthreads();

    float rowmax = smax[0];
    #pragma unroll
    for (int w = 1; w < NWARPS; w++) rowmax = fmaxf(rowmax, smax[w]);
    // Fully-masked row: rowmax = -inf would give NaN in (v - rowmax); clamp.
    if (!(rowmax > NEG_INF)) rowmax = 0.0f;

    // --- exp + sum; exp(-inf - rowmax) = 0 on masked lanes ---
    float sum = 0.0f;
    #pragma unroll
    for (int i = 0; i < EPT; i++) {
        vals[i] = __expf(vals[i] - rowmax);   // overwrite in place: p[i]
        sum += vals[i];
    }
    #pragma unroll
    for (int o = 16; o > 0; o >>= 1)
        sum += __shfl_xor_sync(0xffffffffu, sum, o);
    if (lane == 0) ssum[warp] = sum;
    __syncthreads();

    float s = ssum[0];
    #pragma unroll
    for (int w = 1; w < NWARPS; w++) s += ssum[w];
    const float inv = (s > 0.0f) ? (1.0f / s) : 0.0f;   // fully-masked -> zeros

    // --- normalize + streaming writes (4x STG.128) ---
    __stcs(&out4[t],
           make_float4(vals[0]*inv, vals[1]*inv, vals[2]*inv, vals[3]*inv));
    __stcs(&out4[t + THREADS],
           make_float4(vals[4]*inv, vals[5]*inv, vals[6]*inv, vals[7]*inv));
    __stcs(&out4[t + 2 * THREADS],
           make_float4(vals[8]*inv, vals[9]*inv, vals[10]*inv, vals[11]*inv));
    __stcs(&out4[t + 3 * THREADS],
           make_float4(vals[12]*inv, vals[13]*inv, vals[14]*inv, vals[15]*inv));
}

extern "C" void kernel_launch(void* const* d_in, const int* in_sizes, int n_in,
                              void* d_out, int out_size)
{
    const float* features = (const float*)d_in[0];
    const int*   OD       = (const int*)d_in[1];
    float*       out      = (float*)d_out;

    const int rows = in_sizes[0] / ROW_LEN;   // 32*2048 = 65536
    sparse_softmax_kernel<<<rows, THREADS>>>(features, OD, out);
}